// round 2
// baseline (speedup 1.0000x reference)
#include <cuda_runtime.h>
#include <math.h>

#define N_DRUG 11000
#define N_PRO  1000
#define NTOT   12000
#define NE     192000
#define OFF_MU 144000000L
#define OFF_LV 145536000L

// ---------------- static scratch (no allocations allowed) ----------------
__device__ float g_d1[N_DRUG*128];
__device__ float g_d2[N_DRUG*256];
__device__ float g_X[NTOT*128];
__device__ float g_W2d[N_PRO*256];
__device__ float g_Gt[26*256*128];
__device__ float g_M[26L*N_PRO*128];
__device__ float g_pbias[128];
__device__ float g_XW1[NTOT*256];
__device__ float g_H1b[NTOT*256];
__device__ float g_HW[NTOT*256];
__device__ float g_gc23[256*256];
__device__ int   g_cnt[NTOT];
__device__ int   g_rp[NTOT+1];
__device__ int   g_cur[NTOT];
__device__ int   g_ccol[NE];
__device__ float g_cval[NE];

// ---------------- f32x2 helpers ----------------
__device__ __forceinline__ unsigned long long dupf2(float a) {
    unsigned long long r;
    asm("mov.b64 %0, {%1, %1};" : "=l"(r) : "f"(a));
    return r;
}
__device__ __forceinline__ void fma2(unsigned long long& d, unsigned long long a, unsigned long long b) {
    asm("fma.rn.f32x2 %0, %1, %2, %0;" : "+l"(d) : "l"(a), "l"(b));
}

// ---------------- CSR build ----------------
__global__ void zero_cnt_kernel() {
    int i = blockIdx.x * 256 + threadIdx.x;
    if (i < NTOT) g_cnt[i] = 0;
}
__global__ void count_kernel(const int* __restrict__ rows) {
    int e = blockIdx.x * 256 + threadIdx.x;
    if (e < NE) atomicAdd(&g_cnt[rows[e]], 1);
}
__global__ void scan_kernel() {
    __shared__ int sums[1024];
    int tid = threadIdx.x;
    const int CH = (NTOT + 1023) / 1024;   // 12
    int base = tid * CH;
    int s = 0;
    for (int i = 0; i < CH; i++) { int idx = base + i; if (idx < NTOT) s += g_cnt[idx]; }
    sums[tid] = s;
    __syncthreads();
    for (int off = 1; off < 1024; off <<= 1) {
        int v = 0;
        if (tid >= off) v = sums[tid - off];
        __syncthreads();
        sums[tid] += v;
        __syncthreads();
    }
    int prefix = (tid == 0) ? 0 : sums[tid - 1];
    for (int i = 0; i < CH; i++) {
        int idx = base + i;
        if (idx < NTOT) { g_rp[idx] = prefix; g_cur[idx] = prefix; prefix += g_cnt[idx]; }
    }
    if (tid == 1023) g_rp[NTOT] = NE;
}
__global__ void scatter_kernel(const int* __restrict__ rows, const int* __restrict__ cols,
                               const float* __restrict__ vals) {
    int e = blockIdx.x * 256 + threadIdx.x;
    if (e < NE) {
        int r = rows[e];
        int pos = atomicAdd(&g_cur[r], 1);
        g_ccol[pos] = cols[e];
        g_cval[pos] = vals[e];
    }
}

// ---------------- generic tiled GEMM: C[M,N] = A[M,K] @ B[K,N] (+bias,relu) ---
// 128x64 tile, 256 threads, 8x4 microtile, optional batch via blockIdx.z.
__global__ __launch_bounds__(256) void gemm_kernel(
    const float* __restrict__ A, const float* __restrict__ B,
    const float* __restrict__ bias, float* __restrict__ C,
    int M, int N, int K, int relu,
    long sA, long sB, long sC)
{
    A += (long)blockIdx.z * sA;
    B += (long)blockIdx.z * sB;
    C += (long)blockIdx.z * sC;
    __shared__ float As[16][132];
    __shared__ float Bs[16][68];
    int tid = threadIdx.x;
    int tx = tid & 15, ty = tid >> 4;
    int m0 = blockIdx.y * 128, n0 = blockIdx.x * 64;
    float acc[8][4];
#pragma unroll
    for (int i = 0; i < 8; i++)
#pragma unroll
        for (int j = 0; j < 4; j++) acc[i][j] = 0.f;

    int ktiles = (K + 15) >> 4;
    for (int kt = 0; kt < ktiles; kt++) {
        int k0 = kt << 4;
#pragma unroll
        for (int l = 0; l < 8; l++) {
            int idx = tid + l * 256;
            int k = idx & 15, m = idx >> 4;
            int gm = m0 + m, gk = k0 + k;
            As[k][m] = (gm < M && gk < K) ? A[(long)gm * K + gk] : 0.f;
        }
#pragma unroll
        for (int l = 0; l < 4; l++) {
            int idx = tid + l * 256;
            int n = idx & 63, k = idx >> 6;
            int gk = k0 + k, gn = n0 + n;
            Bs[k][n] = (gk < K && gn < N) ? B[(long)gk * N + gn] : 0.f;
        }
        __syncthreads();
#pragma unroll
        for (int k = 0; k < 16; k++) {
            float4 a0 = *(const float4*)&As[k][ty * 8];
            float4 a1 = *(const float4*)&As[k][ty * 8 + 4];
            float4 b  = *(const float4*)&Bs[k][tx * 4];
            float av[8] = {a0.x, a0.y, a0.z, a0.w, a1.x, a1.y, a1.z, a1.w};
            float bv[4] = {b.x, b.y, b.z, b.w};
#pragma unroll
            for (int i = 0; i < 8; i++)
#pragma unroll
                for (int j = 0; j < 4; j++) acc[i][j] += av[i] * bv[j];
        }
        __syncthreads();
    }
#pragma unroll
    for (int i = 0; i < 8; i++) {
        int gm = m0 + ty * 8 + i;
        if (gm >= M) continue;
#pragma unroll
        for (int j = 0; j < 4; j++) {
            int gn = n0 + tx * 4 + j;
            if (gn >= N) continue;
            float v = acc[i][j];
            if (bias) v += bias[gn];
            if (relu) v = fmaxf(v, 0.f);
            C[(long)gm * N + gn] = v;
        }
    }
}

// ---------------- protein branch ----------------
__global__ void repack_w_kernel(const float* __restrict__ conv_w) {
    int idx = blockIdx.x * 256 + threadIdx.x;   // 256000
    if (idx < N_PRO * 256) {
        int i = idx >> 8, ok = idx & 255;
        int o = ok >> 3, k = ok & 7;
        g_W2d[idx] = conv_w[((long)o * N_PRO + i) * 8 + k];
    }
}
// Gt[t][ok][f] = sum_h emb[t, h+k] * fc_w[(o*121+h)*128 + f]
__global__ void g_kernel(const float* __restrict__ emb, const float* __restrict__ fc_w) {
    int idx = blockIdx.x;          // t*256 + ok   (26*256 blocks)
    int t = idx >> 8, ok = idx & 255;
    int o = ok >> 3, kk = ok & 7;
    int f = threadIdx.x;           // 128
    __shared__ float e[128];
    if (f < 121) e[f] = emb[t * 128 + kk + f];
    __syncthreads();
    float acc = 0.f;
#pragma unroll 4
    for (int h = 0; h < 121; h++)
        acc += e[h] * fc_w[(o * 121 + h) * 128 + f];
    g_Gt[(long)idx * 128 + f] = acc;
}
__global__ void pbias_kernel(const float* __restrict__ fc_b, const float* __restrict__ conv_b,
                             const float* __restrict__ fc_w) {
    int f = threadIdx.x;   // 128
    float acc = fc_b[f];
    for (int o = 0; o < 32; o++) {
        float cb = conv_b[o];
        for (int h = 0; h < 121; h++) acc += cb * fc_w[(o * 121 + h) * 128 + f];
    }
    g_pbias[f] = acc;
}
// X[11000+p][f] = pbias[f] + sum_i M[tok(p,i)][i][f]
__global__ void protein_gather_kernel(const int* __restrict__ pro_x) {
    int p = blockIdx.x, f = threadIdx.x;   // 1000 blocks x 128
    __shared__ int tok[128];
    float acc = g_pbias[f];
    for (int c = 0; c < 1000; c += 128) {
        int n = min(128, 1000 - c);
        if (f < n) tok[f] = pro_x[p * 1000 + c + f];
        __syncthreads();
#pragma unroll 8
        for (int ii = 0; ii < n; ii++) {
            int t = tok[ii];
            acc += g_M[((long)t * N_PRO + c + ii) * 128 + f];
        }
        __syncthreads();
    }
    g_X[(long)(N_DRUG + p) * 128 + f] = acc;
}
__global__ void repack_gc23_kernel(const float* __restrict__ gc2, const float* __restrict__ gc3) {
    int idx = blockIdx.x * 256 + threadIdx.x;   // 256*256
    int r = idx >> 8, c = idx & 255;
    g_gc23[idx] = (c < 128) ? gc2[r * 128 + c] : gc3[r * 128 + c - 128];
}

// ---------------- SpMM (CSR gather), F=256, optional split output -----------
__global__ void spmm256_kernel(const float* __restrict__ Xin,
                               float* __restrict__ out1, float* __restrict__ out2, int relu) {
    int r = blockIdx.x;
    int f = threadIdx.x;   // 256
    int e0 = g_rp[r], e1 = g_rp[r + 1];
    float acc = 0.f;
    for (int e = e0; e < e1; e++) {
        int c = g_ccol[e];
        float v = g_cval[e];
        acc += v * Xin[(long)c * 256 + f];
    }
    if (relu) acc = fmaxf(acc, 0.f);
    if (out2) {
        if (f < 128) out1[(long)r * 128 + f] = acc;
        else         out2[(long)r * 128 + f - 128] = acc;
    } else {
        out1[(long)r * 256 + f] = acc;
    }
}

// ---------------- SYRK: C = Z Z^T, Z[12000,128], symmetric, FFMA2 ----------
__global__ __launch_bounds__(256, 2) void syrk_kernel(const float* __restrict__ Z,
                                                      float* __restrict__ C) {
    const int T = 94;
    int p = blockIdx.x;
    int ti = (int)((2.0 * T + 1.0 - sqrt((2.0 * T + 1.0) * (2.0 * T + 1.0) - 8.0 * p)) * 0.5);
    if (ti < 0) ti = 0;
    if (ti > T - 1) ti = T - 1;
    while (ti > 0 && ti * T - ti * (ti - 1) / 2 > p) ti--;
    while ((ti + 1) * T - ((ti + 1) * ti) / 2 <= p) ti++;
    int tj = ti + (p - (ti * T - ti * (ti - 1) / 2));
    long i0 = (long)ti * 128, j0 = (long)tj * 128;

    __shared__ float As[16][132];
    __shared__ float Bs[16][132];
    __shared__ float S[32][129];

    int tid = threadIdx.x;
    int tx = tid & 15, ty = tid >> 4;
    unsigned long long acc[8][4];
#pragma unroll
    for (int i = 0; i < 8; i++)
#pragma unroll
        for (int j = 0; j < 4; j++) acc[i][j] = 0ull;

    int r  = tid >> 1;
    int kh = (tid & 1) * 8;

    for (int k0 = 0; k0 < 128; k0 += 16) {
        {
            long gr = i0 + r;
            float4 v0 = make_float4(0.f, 0.f, 0.f, 0.f), v1 = v0;
            if (gr < NTOT) {
                const float4* src = (const float4*)(Z + gr * 128 + k0 + kh);
                v0 = src[0]; v1 = src[1];
            }
            As[kh + 0][r] = v0.x; As[kh + 1][r] = v0.y; As[kh + 2][r] = v0.z; As[kh + 3][r] = v0.w;
            As[kh + 4][r] = v1.x; As[kh + 5][r] = v1.y; As[kh + 6][r] = v1.z; As[kh + 7][r] = v1.w;
            gr = j0 + r;
            v0 = make_float4(0.f, 0.f, 0.f, 0.f); v1 = v0;
            if (gr < NTOT) {
                const float4* src = (const float4*)(Z + gr * 128 + k0 + kh);
                v0 = src[0]; v1 = src[1];
            }
            Bs[kh + 0][r] = v0.x; Bs[kh + 1][r] = v0.y; Bs[kh + 2][r] = v0.z; Bs[kh + 3][r] = v0.w;
            Bs[kh + 4][r] = v1.x; Bs[kh + 5][r] = v1.y; Bs[kh + 6][r] = v1.z; Bs[kh + 7][r] = v1.w;
        }
        __syncthreads();
#pragma unroll
        for (int k = 0; k < 16; k++) {
            float4 a0 = *(const float4*)&As[k][ty * 8];
            float4 a1 = *(const float4*)&As[k][ty * 8 + 4];
            unsigned long long aa[8];
            aa[0] = dupf2(a0.x); aa[1] = dupf2(a0.y); aa[2] = dupf2(a0.z); aa[3] = dupf2(a0.w);
            aa[4] = dupf2(a1.x); aa[5] = dupf2(a1.y); aa[6] = dupf2(a1.z); aa[7] = dupf2(a1.w);
            const ulonglong2* bp = (const ulonglong2*)&Bs[k][tx * 8];
            ulonglong2 b01 = bp[0], b23 = bp[1];
            unsigned long long bb[4] = {b01.x, b01.y, b23.x, b23.y};
#pragma unroll
            for (int i = 0; i < 8; i++)
#pragma unroll
                for (int j = 0; j < 4; j++) fma2(acc[i][j], aa[i], bb[j]);
        }
        __syncthreads();
    }

    float cf[8][8];
#pragma unroll
    for (int i = 0; i < 8; i++)
#pragma unroll
        for (int j = 0; j < 4; j++)
            asm("mov.b64 {%0, %1}, %2;"
                : "=f"(cf[i][2 * j]), "=f"(cf[i][2 * j + 1]) : "l"(acc[i][j]));

    bool full = (i0 + 128 <= NTOT) && (j0 + 128 <= NTOT);

    if (full) {
#pragma unroll
        for (int i = 0; i < 8; i++) {
            long gm = i0 + ty * 8 + i;
            float4* dst = (float4*)(C + gm * (long)NTOT + j0 + tx * 8);
            dst[0] = make_float4(cf[i][0], cf[i][1], cf[i][2], cf[i][3]);
            dst[1] = make_float4(cf[i][4], cf[i][5], cf[i][6], cf[i][7]);
        }
    } else {
#pragma unroll
        for (int i = 0; i < 8; i++) {
            long gm = i0 + ty * 8 + i;
            if (gm >= NTOT) continue;
#pragma unroll
            for (int j = 0; j < 8; j++) {
                long gn = j0 + tx * 8 + j;
                if (gn >= NTOT) continue;
                C[gm * (long)NTOT + gn] = cf[i][j];
            }
        }
    }

    if (ti != tj) {
        if (full) {
#pragma unroll
            for (int ic = 0; ic < 4; ic++) {
                __syncthreads();
                if ((ty >> 2) == ic) {
                    int iw = (ty & 3) * 8;
#pragma unroll
                    for (int i = 0; i < 8; i++)
#pragma unroll
                        for (int j = 0; j < 8; j++)
                            S[iw + i][tx * 8 + j] = cf[i][j];
                }
                __syncthreads();
                int jj = tid >> 1;
                int off = (tid & 1) * 16;
                float* dst = C + (j0 + jj) * (long)NTOT + i0 + ic * 32 + off;
#pragma unroll
                for (int q = 0; q < 4; q++) {
                    float4 v;
                    v.x = S[off + q * 4 + 0][jj];
                    v.y = S[off + q * 4 + 1][jj];
                    v.z = S[off + q * 4 + 2][jj];
                    v.w = S[off + q * 4 + 3][jj];
                    ((float4*)dst)[q] = v;
                }
            }
        } else {
#pragma unroll
            for (int i = 0; i < 8; i++) {
                long gm = i0 + ty * 8 + i;
                if (gm >= NTOT) continue;
#pragma unroll
                for (int j = 0; j < 8; j++) {
                    long gn = j0 + tx * 8 + j;
                    if (gn >= NTOT) continue;
                    C[gn * (long)NTOT + gm] = cf[i][j];
                }
            }
        }
    }
}

// ---------------- host ----------------
extern "C" void kernel_launch(void* const* d_in, const int* in_sizes, int n_in,
                              void* d_out, int out_size) {
    const float* drug_x = (const float*)d_in[0];
    const int*   pro_x  = (const int*)d_in[1];
    const int*   arows  = (const int*)d_in[2];
    const int*   acols  = (const int*)d_in[3];
    const float* avals  = (const float*)d_in[4];
    const float* w1     = (const float*)d_in[5];
    const float* b1     = (const float*)d_in[6];
    const float* w2     = (const float*)d_in[7];
    const float* b2     = (const float*)d_in[8];
    const float* w3     = (const float*)d_in[9];
    const float* b3     = (const float*)d_in[10];
    const float* emb_xt = (const float*)d_in[11];
    const float* conv_w = (const float*)d_in[12];
    const float* conv_b = (const float*)d_in[13];
    const float* fc_w   = (const float*)d_in[14];
    const float* fc_b   = (const float*)d_in[15];
    const float* gc1_w  = (const float*)d_in[16];
    const float* gc2_w  = (const float*)d_in[17];
    const float* gc3_w  = (const float*)d_in[18];
    float* out = (float*)d_out;

    float *pd1, *pd2, *pX, *pW2d, *pGt, *pM, *pXW1, *pH1, *pHW, *pgc23;
    cudaGetSymbolAddress((void**)&pd1,  g_d1);
    cudaGetSymbolAddress((void**)&pd2,  g_d2);
    cudaGetSymbolAddress((void**)&pX,   g_X);
    cudaGetSymbolAddress((void**)&pW2d, g_W2d);
    cudaGetSymbolAddress((void**)&pGt,  g_Gt);
    cudaGetSymbolAddress((void**)&pM,   g_M);
    cudaGetSymbolAddress((void**)&pXW1, g_XW1);
    cudaGetSymbolAddress((void**)&pH1,  g_H1b);
    cudaGetSymbolAddress((void**)&pHW,  g_HW);
    cudaGetSymbolAddress((void**)&pgc23, g_gc23);

    // CSR build
    zero_cnt_kernel<<<47, 256>>>();
    count_kernel<<<750, 256>>>(arows);
    scan_kernel<<<1, 1024>>>();
    scatter_kernel<<<750, 256>>>(arows, acols, avals);

    // drug MLP
    gemm_kernel<<<dim3(2, 86, 1), 256>>>(drug_x, w1, b1, pd1, N_DRUG, 128, 167, 1, 0, 0, 0);
    gemm_kernel<<<dim3(4, 86, 1), 256>>>(pd1, w2, b2, pd2, N_DRUG, 256, 128, 1, 0, 0, 0);
    gemm_kernel<<<dim3(2, 86, 1), 256>>>(pd2, w3, b3, pX, N_DRUG, 128, 256, 1, 0, 0, 0);

    // protein branch (conv+fc refactored)
    repack_w_kernel<<<1000, 256>>>(conv_w);
    g_kernel<<<26 * 256, 128>>>(emb_xt, fc_w);
    pbias_kernel<<<1, 128>>>(fc_b, conv_b, fc_w);
    gemm_kernel<<<dim3(2, 8, 26), 256>>>(pW2d, pGt, nullptr, pM, N_PRO, 128, 256, 0,
                                         0, 256L * 128, (long)N_PRO * 128);
    protein_gather_kernel<<<1000, 128>>>(pro_x);

    // GCN encoder
    repack_gc23_kernel<<<256, 256>>>(gc2_w, gc3_w);
    gemm_kernel<<<dim3(4, 94, 1), 256>>>(pX, gc1_w, nullptr, pXW1, NTOT, 256, 128, 0, 0, 0, 0);
    spmm256_kernel<<<NTOT, 256>>>(pXW1, pH1, nullptr, 1);
    gemm_kernel<<<dim3(4, 94, 1), 256>>>(pH1, pgc23, nullptr, pHW, NTOT, 256, 256, 0, 0, 0, 0);
    spmm256_kernel<<<NTOT, 256>>>(pHW, out + OFF_MU, out + OFF_LV, 0);

    // decoder: adj_rec = Z Z^T with Z = mu (read directly from d_out)
    syrk_kernel<<<4465, 256>>>(out + OFF_MU, out);
}